// round 14
// baseline (speedup 1.0000x reference)
#include <cuda_runtime.h>
#include <cuda_bf16.h>
#include <cstdint>

#define DIMV   2048
#define SV     4
#define NTV    5          // S + V
#define NV     2048
#define BV     4
#define TPB    128
#define NWARP  (TPB / 32)
#define CHUNKS (DIMV / (4 * TPB))   // 4 float4 chunks per thread per row
#define QUADS  (DIMV / 4)
#define ROWBYTES (DIMV * 4)         // 8192 bytes per stream row
#define EPSV   1e-5f

// Scratch (no device allocation allowed).
// g_gp[j][q]: uint4 holding gates t=2j,2j+1 for dim-quad q, bf16-packed.
__device__ uint4 g_gp[3][QUADS];
__device__ float g_gsum[6];        // column sums of the ROUNDED gate values

__global__ void prep_kernel(const float* __restrict__ w,
                            const float* __restrict__ afn,
                            const float* __restrict__ bfn) {
    __shared__ float sred[16][6];
    const int tid = threadIdx.x;          // 512 threads, 1 block; one per dim-quad
    const int d0  = tid * 4;

    float gv[6][4];
#pragma unroll
    for (int i = 0; i < 4; i++) {
        float wv = w[d0 + i];
#pragma unroll
        for (int t = 0; t < NTV; t++)
            gv[t][i] = wv * afn[(d0 + i) * NTV + t];
        gv[5][i] = wv * bfn[d0 + i];
    }

    float part[6];
#pragma unroll
    for (int j = 0; j < 3; j++) {
        const int t0 = 2 * j, t1 = 2 * j + 1;
        __nv_bfloat162 hx = __floats2bfloat162_rn(gv[t0][0], gv[t0][1]);
        __nv_bfloat162 hy = __floats2bfloat162_rn(gv[t0][2], gv[t0][3]);
        __nv_bfloat162 hz = __floats2bfloat162_rn(gv[t1][0], gv[t1][1]);
        __nv_bfloat162 hw = __floats2bfloat162_rn(gv[t1][2], gv[t1][3]);
        uint4 u;
        u.x = *reinterpret_cast<unsigned*>(&hx);
        u.y = *reinterpret_cast<unsigned*>(&hy);
        u.z = *reinterpret_cast<unsigned*>(&hz);
        u.w = *reinterpret_cast<unsigned*>(&hw);
        g_gp[j][tid] = u;
        float2 fx = __bfloat1622float2(hx), fy = __bfloat1622float2(hy);
        float2 fz = __bfloat1622float2(hz), fw = __bfloat1622float2(hw);
        part[t0] = fx.x + fx.y + fy.x + fy.y;
        part[t1] = fz.x + fz.y + fw.x + fw.y;
    }

#pragma unroll
    for (int u = 0; u < 6; u++)
#pragma unroll
        for (int o = 16; o > 0; o >>= 1)
            part[u] += __shfl_xor_sync(0xffffffffu, part[u], o);
    if ((tid & 31) == 0)
#pragma unroll
        for (int u = 0; u < 6; u++) sred[tid >> 5][u] = part[u];
    __syncthreads();
    if (tid < 6) {
        float tot = 0.f;
#pragma unroll
        for (int wp = 0; wp < 16; wp++) tot += sred[wp][tid];
        g_gsum[tid] = tot;
    }
}

__device__ __forceinline__ uint32_t smem_u32(const void* p) {
    uint32_t a;
    asm("{ .reg .u64 t; cvta.to.shared.u64 t, %1; cvt.u32.u64 %0, t; }"
        : "=r"(a) : "l"(p));
    return a;
}

__global__ __launch_bounds__(TPB, 6) void hyper_kernel(
    const float* __restrict__ res,
    const float* __restrict__ static_beta,
    const float* __restrict__ static_alpha,
    const float* __restrict__ p_ascale,
    const float* __restrict__ p_bscale,
    float* __restrict__ out)
{
    __shared__ alignas(128) float tile[SV][DIMV];   // 32 KB residual/output tile
    __shared__ float sred[NWARP][32];
    __shared__ alignas(8) uint64_t mbar;

    const int tid  = threadIdx.x;
    const int warp = tid >> 5;
    const int lane = tid & 31;

    const int token = blockIdx.x;              // 0 .. B*N-1
    const int b = token >> 11;
    const int n = token & (NV - 1);
    const size_t rowstride = (size_t)NV * DIMV;
    const float* base  = res + (size_t)(b * SV) * rowstride + (size_t)n * DIMV;
    float*       obase = out + (size_t)(b * SV) * rowstride + (size_t)n * DIMV;

    const uint32_t mb = smem_u32(&mbar);

    // ---- Kick off the TMA tile fill for pass C, then IMMEDIATELY start
    //      pass A via LDG from global (L2 dedups with the TMA stream). ----
    if (tid == 0) {
        asm volatile("mbarrier.init.shared.b64 [%0], %1;" :: "r"(mb), "r"(1) : "memory");
        asm volatile("fence.proxy.async.shared::cta;" ::: "memory");
        asm volatile("mbarrier.arrive.expect_tx.shared.b64 _, [%0], %1;"
                     :: "r"(mb), "r"(SV * ROWBYTES) : "memory");
#pragma unroll
        for (int s = 0; s < SV; s++) {
            const uint32_t dst = smem_u32(&tile[s][0]);
            const float* src = base + (size_t)s * rowstride;
            asm volatile(
                "cp.async.bulk.shared::cta.global.mbarrier::complete_tx::bytes "
                "[%0], [%1], %2, [%3];"
                :: "r"(dst), "l"(src), "r"(ROWBYTES), "r"(mb) : "memory");
        }
    }

    // ---- Fused pass A from GLOBAL: sum/ssq + 6 gate dots.
    //      acc[s*8+f]: f 0=sum 1=ssq 2..7=dots t0..t5 ----
    float acc[32];
#pragma unroll
    for (int u = 0; u < 32; u++) acc[u] = 0.f;

#pragma unroll
    for (int k = 0; k < CHUNKS; k++) {
        const int idx = tid + k * TPB;
        float4 v[SV];
#pragma unroll
        for (int s = 0; s < SV; s++)
            v[s] = __ldg(&((const float4*)(base + (size_t)s * rowstride))[idx]);

#pragma unroll
        for (int s = 0; s < SV; s++) {
            acc[s * 8 + 0] += v[s].x + v[s].y + v[s].z + v[s].w;
            acc[s * 8 + 1] += v[s].x * v[s].x + v[s].y * v[s].y
                            + v[s].z * v[s].z + v[s].w * v[s].w;
        }

#pragma unroll
        for (int j = 0; j < 3; j++) {
            uint4 p = g_gp[j][idx];
            float2 fx = __bfloat1622float2(*reinterpret_cast<__nv_bfloat162*>(&p.x));
            float2 fy = __bfloat1622float2(*reinterpret_cast<__nv_bfloat162*>(&p.y));
            float2 fz = __bfloat1622float2(*reinterpret_cast<__nv_bfloat162*>(&p.z));
            float2 fw = __bfloat1622float2(*reinterpret_cast<__nv_bfloat162*>(&p.w));
#pragma unroll
            for (int s = 0; s < SV; s++) {
                acc[s * 8 + 2 + 2 * j]     += v[s].x * fx.x + v[s].y * fx.y
                                            + v[s].z * fy.x + v[s].w * fy.y;
                acc[s * 8 + 2 + 2 * j + 1] += v[s].x * fz.x + v[s].y * fz.y
                                            + v[s].z * fw.x + v[s].w * fw.y;
            }
        }
    }

    // ---- Butterfly reduction: 32 values across 32 lanes in 31 shuffles ----
    {
        int cnt = 32;
#pragma unroll
        for (int o = 1; o <= 16; o <<= 1) {
            const int h = cnt >> 1;
            const bool up = (lane & o) != 0;
#pragma unroll
            for (int i = 0; i < h; i++) {
                float send = up ? acc[i] : acc[i + h];
                float recv = __shfl_xor_sync(0xffffffffu, send, o);
                float keep = up ? acc[i + h] : acc[i];
                acc[i] = keep + recv;
            }
            cnt = h;
        }
    }
    const int vidx = ((lane & 1) << 4) | ((lane & 2) << 2) | (lane & 4)
                   | ((lane & 8) >> 2) | ((lane & 16) >> 4);
    sred[warp][vidx] = acc[0];
    __syncthreads();

    // ---- Redundant per-warp finalize: lane u owns value u = s*8+f ----
    float tot = sred[0][lane];
#pragma unroll
    for (int w = 1; w < NWARP; w++) tot += sred[w][lane];

    const int s_own = lane >> 3;
    const int f     = lane & 7;
    const float tsum = __shfl_sync(0xffffffffu, tot, (lane & 24) | 0);
    const float tssq = __shfl_sync(0xffffffffu, tot, (lane & 24) | 1);
    const float mu   = tsum * (1.f / DIMV);
    const float var  = tssq * (1.f / DIMV) - mu * mu;
    const float rsig = rsqrtf(var + EPSV);

    const int jf = (f >= 2) ? (f - 2) : 0;     // clamped for safe loads
    const float gs   = g_gsum[jf];
    const float dotc = (tot - mu * gs) * rsig;
    const float th   = tanhf(dotc);
    float ab;
    if (f < 7) ab = th * p_ascale[0] + static_alpha[s_own * NTV + jf];
    else       ab = th * p_bscale[0] + static_beta[s_own];
    // lanes f=2..6 hold alpha[s][0..4]; lane f=7 holds beta[s]; f<2 garbage.

    // Fold into 4x4 mix matrix on lanes 0..15, then broadcast.
    const int cs = lane >> 2, csp = lane & 3;
    const float beta_s  = __shfl_sync(0xffffffffu, ab, cs * 8 + 7);
    const float alp_sp0 = __shfl_sync(0xffffffffu, ab, csp * 8 + 2);
    const float alp_sps = __shfl_sync(0xffffffffu, ab, csp * 8 + 3 + cs);
    const float Cl = beta_s * alp_sp0 + alp_sps;   // valid on lanes 0..15

    float Cm[SV][SV];
#pragma unroll
    for (int s = 0; s < SV; s++)
#pragma unroll
        for (int sp = 0; sp < SV; sp++)
            Cm[s][sp] = __shfl_sync(0xffffffffu, Cl, s * 4 + sp);

    // ---- Wait for the TMA tile (long since landed — pass A covered it) ----
    {
        uint32_t done;
        do {
            asm volatile(
                "{\n\t.reg .pred p;\n\t"
                "mbarrier.try_wait.parity.acquire.cta.shared::cta.b64 p, [%1], %2, 0x989680;\n\t"
                "selp.b32 %0, 1, 0, p;\n\t}"
                : "=r"(done) : "r"(mb), "r"(0) : "memory");
        } while (!done);
    }

    // ---- Pass C: read tile, 4x4 mix, write results back IN PLACE (each
    //      thread reads all 4 stream values for its idx before overwriting,
    //      and each idx is owned by exactly one thread — race-free). ----
#pragma unroll
    for (int k = 0; k < CHUNKS; k++) {
        const int idx = tid + k * TPB;
        float4 vc[SV];
#pragma unroll
        for (int s = 0; s < SV; s++)
            vc[s] = ((const float4*)tile[s])[idx];
#pragma unroll
        for (int s = 0; s < SV; s++) {
            float4 o;
            o.x = Cm[s][0] * vc[0].x; o.y = Cm[s][0] * vc[0].y;
            o.z = Cm[s][0] * vc[0].z; o.w = Cm[s][0] * vc[0].w;
#pragma unroll
            for (int sp = 1; sp < SV; sp++) {
                o.x += Cm[s][sp] * vc[sp].x;
                o.y += Cm[s][sp] * vc[sp].y;
                o.z += Cm[s][sp] * vc[sp].z;
                o.w += Cm[s][sp] * vc[sp].w;
            }
            ((float4*)tile[s])[idx] = o;
        }
    }

    // Make the STS visible to the async proxy, then bulk-store SMEM -> GMEM.
    asm volatile("fence.proxy.async.shared::cta;" ::: "memory");
    __syncthreads();
    if (tid == 0) {
#pragma unroll
        for (int s = 0; s < SV; s++) {
            const uint32_t src = smem_u32(&tile[s][0]);
            float* dst = obase + (size_t)s * rowstride;
            asm volatile(
                "cp.async.bulk.global.shared::cta.bulk_group [%0], [%1], %2;"
                :: "l"(dst), "r"(src), "r"(ROWBYTES) : "memory");
        }
        asm volatile("cp.async.bulk.commit_group;" ::: "memory");
        asm volatile("cp.async.bulk.wait_group 0;" ::: "memory");
    }
}

extern "C" void kernel_launch(void* const* d_in, const int* in_sizes, int n_in,
                              void* d_out, int out_size) {
    const float* res    = (const float*)d_in[0];
    const float* w      = (const float*)d_in[1];
    const float* sbeta  = (const float*)d_in[2];
    const float* salpha = (const float*)d_in[3];
    const float* afn    = (const float*)d_in[4];
    const float* ascale = (const float*)d_in[5];
    const float* bfn    = (const float*)d_in[6];
    const float* bscale = (const float*)d_in[7];
    float* out = (float*)d_out;

    prep_kernel<<<1, 512>>>(w, afn, bfn);
    hyper_kernel<<<BV * NV, TPB>>>(res, sbeta, salpha, ascale, bscale, out);
}

// round 15
// speedup vs baseline: 1.1074x; 1.1074x over previous
#include <cuda_runtime.h>
#include <cuda_bf16.h>
#include <cstdint>

#define DIMV   2048
#define SV     4
#define NTV    5          // S + V
#define NV     2048
#define BV     4
#define TPB    128
#define NWARP  (TPB / 32)
#define CHUNKS (DIMV / (4 * TPB))   // 4 float4 chunks per thread per row
#define QUADS  (DIMV / 4)
#define ROWBYTES (DIMV * 4)         // 8192 bytes per stream row
#define PBLK   16                   // prep blocks
#define EPSV   1e-5f

// Scratch (no device allocation allowed).
// g_gp[j][q]: uint4 holding gates t=2j,2j+1 for dim-quad q, bf16-packed.
__device__ uint4 g_gp[3][QUADS];
__device__ float g_gsum_part[PBLK][6];   // per-prep-block partial column sums

__global__ void prep_kernel(const float* __restrict__ w,
                            const float* __restrict__ afn,
                            const float* __restrict__ bfn) {
    // 16 blocks x 32 threads; thread handles one dim-quad.
    const int lane = threadIdx.x;
    const int q    = blockIdx.x * 32 + lane;
    const int d0   = q * 4;

    float gv[6][4];
#pragma unroll
    for (int i = 0; i < 4; i++) {
        float wv = w[d0 + i];
#pragma unroll
        for (int t = 0; t < NTV; t++)
            gv[t][i] = wv * afn[(d0 + i) * NTV + t];
        gv[5][i] = wv * bfn[d0 + i];
    }

    float part[6];
#pragma unroll
    for (int j = 0; j < 3; j++) {
        const int t0 = 2 * j, t1 = 2 * j + 1;
        __nv_bfloat162 hx = __floats2bfloat162_rn(gv[t0][0], gv[t0][1]);
        __nv_bfloat162 hy = __floats2bfloat162_rn(gv[t0][2], gv[t0][3]);
        __nv_bfloat162 hz = __floats2bfloat162_rn(gv[t1][0], gv[t1][1]);
        __nv_bfloat162 hw = __floats2bfloat162_rn(gv[t1][2], gv[t1][3]);
        uint4 u;
        u.x = *reinterpret_cast<unsigned*>(&hx);
        u.y = *reinterpret_cast<unsigned*>(&hy);
        u.z = *reinterpret_cast<unsigned*>(&hz);
        u.w = *reinterpret_cast<unsigned*>(&hw);
        g_gp[j][q] = u;
        float2 fx = __bfloat1622float2(hx), fy = __bfloat1622float2(hy);
        float2 fz = __bfloat1622float2(hz), fw = __bfloat1622float2(hw);
        part[t0] = fx.x + fx.y + fy.x + fy.y;
        part[t1] = fz.x + fz.y + fw.x + fw.y;
    }

#pragma unroll
    for (int u = 0; u < 6; u++) {
#pragma unroll
        for (int o = 16; o > 0; o >>= 1)
            part[u] += __shfl_xor_sync(0xffffffffu, part[u], o);
        if (lane == 0) g_gsum_part[blockIdx.x][u] = part[u];
    }
}

__device__ __forceinline__ uint32_t smem_u32(const void* p) {
    uint32_t a;
    asm("{ .reg .u64 t; cvta.to.shared.u64 t, %1; cvt.u32.u64 %0, t; }"
        : "=r"(a) : "l"(p));
    return a;
}

__global__ __launch_bounds__(TPB, 6) void hyper_kernel(
    const float* __restrict__ res,
    const float* __restrict__ static_beta,
    const float* __restrict__ static_alpha,
    const float* __restrict__ p_ascale,
    const float* __restrict__ p_bscale,
    float* __restrict__ out)
{
    __shared__ alignas(128) float tile[SV][DIMV];   // 32 KB residual tile (pass C)
    __shared__ float sred[NWARP][32];
    __shared__ alignas(8) uint64_t mbar;

    const int tid  = threadIdx.x;
    const int warp = tid >> 5;
    const int lane = tid & 31;

    const int token = blockIdx.x;              // 0 .. B*N-1
    const int b = token >> 11;
    const int n = token & (NV - 1);
    const size_t rowstride = (size_t)NV * DIMV;
    const float* base  = res + (size_t)(b * SV) * rowstride + (size_t)n * DIMV;
    float*       obase = out + (size_t)(b * SV) * rowstride + (size_t)n * DIMV;

    const uint32_t mb = smem_u32(&mbar);

    // ---- Kick off the TMA tile fill for pass C, then IMMEDIATELY start
    //      pass A via LDG from global (L2 dedups with the TMA stream). ----
    if (tid == 0) {
        asm volatile("mbarrier.init.shared.b64 [%0], %1;" :: "r"(mb), "r"(1) : "memory");
        asm volatile("fence.proxy.async.shared::cta;" ::: "memory");
        asm volatile("mbarrier.arrive.expect_tx.shared.b64 _, [%0], %1;"
                     :: "r"(mb), "r"(SV * ROWBYTES) : "memory");
#pragma unroll
        for (int s = 0; s < SV; s++) {
            const uint32_t dst = smem_u32(&tile[s][0]);
            const float* src = base + (size_t)s * rowstride;
            asm volatile(
                "cp.async.bulk.shared::cta.global.mbarrier::complete_tx::bytes "
                "[%0], [%1], %2, [%3];"
                :: "r"(dst), "l"(src), "r"(ROWBYTES), "r"(mb) : "memory");
        }
    }

    // ---- Fused pass A from GLOBAL: sum/ssq + 6 gate dots.
    //      acc[s*8+f]: f 0=sum 1=ssq 2..7=dots t0..t5 ----
    float acc[32];
#pragma unroll
    for (int u = 0; u < 32; u++) acc[u] = 0.f;

#pragma unroll
    for (int k = 0; k < CHUNKS; k++) {
        const int idx = tid + k * TPB;
        float4 v[SV];
#pragma unroll
        for (int s = 0; s < SV; s++)
            v[s] = __ldg(&((const float4*)(base + (size_t)s * rowstride))[idx]);

#pragma unroll
        for (int s = 0; s < SV; s++) {
            acc[s * 8 + 0] += v[s].x + v[s].y + v[s].z + v[s].w;
            acc[s * 8 + 1] += v[s].x * v[s].x + v[s].y * v[s].y
                            + v[s].z * v[s].z + v[s].w * v[s].w;
        }

#pragma unroll
        for (int j = 0; j < 3; j++) {
            uint4 p = g_gp[j][idx];
            float2 fx = __bfloat1622float2(*reinterpret_cast<__nv_bfloat162*>(&p.x));
            float2 fy = __bfloat1622float2(*reinterpret_cast<__nv_bfloat162*>(&p.y));
            float2 fz = __bfloat1622float2(*reinterpret_cast<__nv_bfloat162*>(&p.z));
            float2 fw = __bfloat1622float2(*reinterpret_cast<__nv_bfloat162*>(&p.w));
#pragma unroll
            for (int s = 0; s < SV; s++) {
                acc[s * 8 + 2 + 2 * j]     += v[s].x * fx.x + v[s].y * fx.y
                                            + v[s].z * fy.x + v[s].w * fy.y;
                acc[s * 8 + 2 + 2 * j + 1] += v[s].x * fz.x + v[s].y * fz.y
                                            + v[s].z * fw.x + v[s].w * fw.y;
            }
        }
    }

    // ---- Butterfly reduction: 32 values across 32 lanes in 31 shuffles ----
    {
        int cnt = 32;
#pragma unroll
        for (int o = 1; o <= 16; o <<= 1) {
            const int h = cnt >> 1;
            const bool up = (lane & o) != 0;
#pragma unroll
            for (int i = 0; i < h; i++) {
                float send = up ? acc[i] : acc[i + h];
                float recv = __shfl_xor_sync(0xffffffffu, send, o);
                float keep = up ? acc[i + h] : acc[i];
                acc[i] = keep + recv;
            }
            cnt = h;
        }
    }
    const int vidx = ((lane & 1) << 4) | ((lane & 2) << 2) | (lane & 4)
                   | ((lane & 8) >> 2) | ((lane & 16) >> 4);
    sred[warp][vidx] = acc[0];
    __syncthreads();

    // ---- Redundant per-warp finalize: lane u owns value u = s*8+f ----
    float tot = sred[0][lane];
#pragma unroll
    for (int w = 1; w < NWARP; w++) tot += sred[w][lane];

    const int s_own = lane >> 3;
    const int f     = lane & 7;
    const float tsum = __shfl_sync(0xffffffffu, tot, (lane & 24) | 0);
    const float tssq = __shfl_sync(0xffffffffu, tot, (lane & 24) | 1);
    const float mu   = tsum * (1.f / DIMV);
    const float var  = tssq * (1.f / DIMV) - mu * mu;
    const float rsig = rsqrtf(var + EPSV);

    const int jf = (f >= 2) ? (f - 2) : 0;     // clamped for safe loads
    float gs = 0.f;
#pragma unroll
    for (int p = 0; p < PBLK; p++) gs += g_gsum_part[p][jf];
    const float dotc = (tot - mu * gs) * rsig;
    const float th   = tanhf(dotc);
    float ab;
    if (f < 7) ab = th * p_ascale[0] + static_alpha[s_own * NTV + jf];
    else       ab = th * p_bscale[0] + static_beta[s_own];
    // lanes f=2..6 hold alpha[s][0..4]; lane f=7 holds beta[s]; f<2 garbage.

    // Fold into 4x4 mix matrix on lanes 0..15, then broadcast.
    const int cs = lane >> 2, csp = lane & 3;
    const float beta_s  = __shfl_sync(0xffffffffu, ab, cs * 8 + 7);
    const float alp_sp0 = __shfl_sync(0xffffffffu, ab, csp * 8 + 2);
    const float alp_sps = __shfl_sync(0xffffffffu, ab, csp * 8 + 3 + cs);
    const float Cl = beta_s * alp_sp0 + alp_sps;   // valid on lanes 0..15

    float Cm[SV][SV];
#pragma unroll
    for (int s = 0; s < SV; s++)
#pragma unroll
        for (int sp = 0; sp < SV; sp++)
            Cm[s][sp] = __shfl_sync(0xffffffffu, Cl, s * 4 + sp);

    // ---- Wait for the TMA tile (long since landed — pass A covered it) ----
    {
        uint32_t done;
        do {
            asm volatile(
                "{\n\t.reg .pred p;\n\t"
                "mbarrier.try_wait.parity.acquire.cta.shared::cta.b64 p, [%1], %2, 0x989680;\n\t"
                "selp.b32 %0, 1, 0, p;\n\t}"
                : "=r"(done) : "r"(mb), "r"(0) : "memory");
        } while (!done);
    }

    // ---- Pass C: re-read residuals from SMEM (no cache gamble), 4x4 mix,
    //      streaming fire-and-forget stores ----
#pragma unroll
    for (int k = 0; k < CHUNKS; k++) {
        const int idx = tid + k * TPB;
        float4 vc[SV];
#pragma unroll
        for (int s = 0; s < SV; s++)
            vc[s] = ((const float4*)tile[s])[idx];
#pragma unroll
        for (int s = 0; s < SV; s++) {
            float4 o;
            o.x = Cm[s][0] * vc[0].x; o.y = Cm[s][0] * vc[0].y;
            o.z = Cm[s][0] * vc[0].z; o.w = Cm[s][0] * vc[0].w;
#pragma unroll
            for (int sp = 1; sp < SV; sp++) {
                o.x += Cm[s][sp] * vc[sp].x;
                o.y += Cm[s][sp] * vc[sp].y;
                o.z += Cm[s][sp] * vc[sp].z;
                o.w += Cm[s][sp] * vc[sp].w;
            }
            __stcs(&((float4*)(obase + (size_t)s * rowstride))[idx], o);
        }
    }
}

extern "C" void kernel_launch(void* const* d_in, const int* in_sizes, int n_in,
                              void* d_out, int out_size) {
    const float* res    = (const float*)d_in[0];
    const float* w      = (const float*)d_in[1];
    const float* sbeta  = (const float*)d_in[2];
    const float* salpha = (const float*)d_in[3];
    const float* afn    = (const float*)d_in[4];
    const float* ascale = (const float*)d_in[5];
    const float* bfn    = (const float*)d_in[6];
    const float* bscale = (const float*)d_in[7];
    float* out = (float*)d_out;

    prep_kernel<<<PBLK, 32>>>(w, afn, bfn);
    hyper_kernel<<<BV * NV, TPB>>>(res, sbeta, salpha, ascale, bscale, out);
}